// round 14
// baseline (speedup 1.0000x reference)
#include <cuda_runtime.h>
#include <cstdint>

#define BB 4
#define MM 112
#define CCH 512
#define CC2 1024
#define LOUT 49
#define NOC 64
#define NSPLIT 256
#define ICPC 4
#define WS_LD 68

__device__ float g_x[BB * CC2 * MM];
__device__ float g_feato[BB * CC2];
__device__ float g_part[NSPLIT][BB * 64 * NOC];
__device__ float g_sw[BB * NOC * LOUT];
__device__ float g_rs[BB * 169];
__device__ float g_feat[BB * 512];
__device__ float g_sink[512];

// ---------------------------------------------------------------------------
// Dummy kernel: positions pool_kernel at launch #4 so ncu (-s 5 -c 1,
// which lands on my 4th launch) finally profiles it. Trivial + deterministic.
// ---------------------------------------------------------------------------
__global__ void dummy_kernel() {
    if (threadIdx.x == 0) g_sink[256 + (blockIdx.x & 0xff)] = 0.0f;
}

// ---------------------------------------------------------------------------
// Kernel 1: fused pool (avg+max over 16x16) + argmax feature selection.
// ---------------------------------------------------------------------------
__global__ void __launch_bounds__(512) pool_kernel(const float* __restrict__ oct) {
    __shared__ float sfv[MM];
    __shared__ float sfm[MM];
    int b = blockIdx.x >> 9, c = blockIdx.x & 511;
    int tid = threadIdx.x, wid = tid >> 5, lane = tid & 31;

    for (int m = wid; m < MM; m += 16) {
        const float4* p = reinterpret_cast<const float4*>(oct)
                        + ((size_t)(b * MM + m) * CCH + c) * 64;
        float4 v0 = p[lane];
        float4 v1 = p[lane + 32];
        float s  = (v0.x + v0.y) + (v0.z + v0.w) + (v1.x + v1.y) + (v1.z + v1.w);
        float mx = fmaxf(fmaxf(fmaxf(v0.x, v0.y), fmaxf(v0.z, v0.w)),
                         fmaxf(fmaxf(v1.x, v1.y), fmaxf(v1.z, v1.w)));
#pragma unroll
        for (int o = 16; o; o >>= 1) {
            s  += __shfl_xor_sync(0xffffffffu, s, o);
            mx  = fmaxf(mx, __shfl_xor_sync(0xffffffffu, mx, o));
        }
        if (lane == 0) { sfv[m] = s * (1.0f / 256.0f); sfm[m] = mx; }
    }
    __syncthreads();

    if (tid < MM) {
        g_x[(b * CC2 + c) * MM + tid]       = sfv[tid];
        g_x[(b * CC2 + 512 + c) * MM + tid] = sfm[tid];
    }

    if (wid == 15) {
        float maxfv = -1e30f, maxfm = -1e30f;
        int idx = 0x7fffffff;
        for (int m = lane; m < MM; m += 32) {
            maxfv = fmaxf(maxfv, sfv[m]);
            float q = sfm[m];
            if (q > maxfm) { maxfm = q; idx = m; }
        }
#pragma unroll
        for (int o = 16; o; o >>= 1) {
            maxfv = fmaxf(maxfv, __shfl_xor_sync(0xffffffffu, maxfv, o));
            float ov = __shfl_xor_sync(0xffffffffu, maxfm, o);
            int   oi = __shfl_xor_sync(0xffffffffu, idx,   o);
            if (ov > maxfm || (ov == maxfm && oi < idx)) { maxfm = ov; idx = oi; }
        }
        if (lane == 0) {
            g_feato[b * CC2 + c]       = maxfv;
            g_feato[b * CC2 + 512 + c] = sfv[idx];
        }
    }
}

// ---------------------------------------------------------------------------
// Kernel 2: split-K tf32 GEMM (cp.async double-buffered W), 256 CTAs.
// ---------------------------------------------------------------------------
__device__ __forceinline__ float to_tf32(float x) {
    uint32_t u;
    asm("cvt.rna.tf32.f32 %0, %1;" : "=r"(u) : "f"(x));
    return __uint_as_float(u);
}

__device__ __forceinline__ void cp16(void* smem_dst, const void* gptr) {
    uint32_t s = (uint32_t)__cvta_generic_to_shared(smem_dst);
    asm volatile("cp.async.cg.shared.global [%0], [%1], 16;" :: "r"(s), "l"(gptr));
}

extern "C" __global__ void __launch_bounds__(256, 2)
gemm_kernel(const float* __restrict__ w) {
    extern __shared__ float sh[];
    float* xs = sh;            // [4][ICPC][128]
    float* ws = sh + 2048;     // [2][64][WS_LD]

    const int tid = threadIdx.x;
    const int split = blockIdx.x;
    const int ic0 = split * ICPC;

#pragma unroll
    for (int i = 0; i < 4; i++) {
        int ii = tid + i * 256;
        int oc = ii >> 4, k4 = ii & 15;
        cp16(ws + oc * WS_LD + k4 * 4,
             w + (size_t)oc * 65536 + (size_t)ic0 * 64 + k4 * 4);
    }
    asm volatile("cp.async.commit_group;");

    for (int i = tid; i < 4 * ICPC * 128; i += 256) {
        int m = i & 127, j = (i >> 7) & (ICPC - 1), b = i >> 9;
        float v = (m < MM) ? g_x[(b * CC2 + ic0 + j) * MM + m] : 0.0f;
        xs[i] = to_tf32(v);
    }

    const int wid = tid >> 5, lane = tid & 31;
    const int b = wid >> 1, mhalf = wid & 1;
    const int g = lane >> 2, t = lane & 3;
    const float* xb = xs + b * ICPC * 128;

    float acc[2][8][4];
#pragma unroll
    for (int a = 0; a < 2; a++)
#pragma unroll
        for (int n = 0; n < 8; n++)
#pragma unroll
            for (int q = 0; q < 4; q++) acc[a][n][q] = 0.0f;

    for (int j = 0; j < ICPC; j++) {
        asm volatile("cp.async.wait_group 0;");
        __syncthreads();
        if (j < ICPC - 1) {
            float* dst = ws + ((j + 1) & 1) * 64 * WS_LD;
#pragma unroll
            for (int i = 0; i < 4; i++) {
                int ii = tid + i * 256;
                int oc = ii >> 4, k4 = ii & 15;
                cp16(dst + oc * WS_LD + k4 * 4,
                     w + (size_t)oc * 65536 + (size_t)(ic0 + j + 1) * 64 + k4 * 4);
            }
            asm volatile("cp.async.commit_group;");
        }
        const float* wb = ws + (j & 1) * 64 * WS_LD;
        const float* xr = xb + j * 128;
#pragma unroll
        for (int k0 = 0; k0 < 64; k0 += 8) {
            uint32_t a0[2], a1[2], a2[2], a3[2];
#pragma unroll
            for (int mt = 0; mt < 2; mt++) {
                int lb = mhalf * 32 + mt * 16 + g;
                a0[mt] = __float_as_uint(xr[lb     + k0 + t]);
                a1[mt] = __float_as_uint(xr[lb + 8 + k0 + t]);
                a2[mt] = __float_as_uint(xr[lb     + k0 + t + 4]);
                a3[mt] = __float_as_uint(xr[lb + 8 + k0 + t + 4]);
            }
#pragma unroll
            for (int nt = 0; nt < 8; nt++) {
                uint32_t b0 = __float_as_uint(wb[(nt * 8 + g) * WS_LD + k0 + t]);
                uint32_t b1 = __float_as_uint(wb[(nt * 8 + g) * WS_LD + k0 + t + 4]);
#pragma unroll
                for (int mt = 0; mt < 2; mt++) {
                    asm volatile(
                        "mma.sync.aligned.m16n8k8.row.col.f32.tf32.tf32.f32 "
                        "{%0,%1,%2,%3}, {%4,%5,%6,%7}, {%8,%9}, {%0,%1,%2,%3};"
                        : "+f"(acc[mt][nt][0]), "+f"(acc[mt][nt][1]),
                          "+f"(acc[mt][nt][2]), "+f"(acc[mt][nt][3])
                        : "r"(a0[mt]), "r"(a1[mt]), "r"(a2[mt]), "r"(a3[mt]),
                          "r"(b0), "r"(b1));
                }
            }
        }
    }

    float* po = &g_part[split][0];
#pragma unroll
    for (int mt = 0; mt < 2; mt++) {
        int row0 = mhalf * 32 + mt * 16 + g;
#pragma unroll
        for (int nt = 0; nt < 8; nt++) {
            int col = nt * 8 + 2 * t;
            if (row0 < LOUT) {
                float2 v01 = make_float2(acc[mt][nt][0], acc[mt][nt][1]);
                *reinterpret_cast<float2*>(po + (size_t)(b * 64 + row0) * 64 + col) = v01;
            }
            if (row0 + 8 < LOUT) {
                float2 v23 = make_float2(acc[mt][nt][2], acc[mt][nt][3]);
                *reinterpret_cast<float2*>(po + (size_t)(b * 64 + row0 + 8) * 64 + col) = v23;
            }
        }
    }
}

// ---------------------------------------------------------------------------
// Kernel 3: split-K reduce over LIVE outputs only (392 blocks) + L2 prefetch.
// lid enumerates (b, l<49, oc); g_part keeps its padded [b][64][oc] layout.
// ---------------------------------------------------------------------------
#define NLIVE (BB * LOUT * NOC)   // 12544
__global__ void __launch_bounds__(256) reduce_kernel(const float* __restrict__ bias,
                                                     const float* __restrict__ wf,
                                                     const float* __restrict__ hw,
                                                     const float* __restrict__ featf) {
    __shared__ float acc[8][32];
    int tid = threadIdx.x;
    int q = tid >> 5, r = tid & 31;
    int lid = blockIdx.x * 32 + r;           // live index
    int oc = lid & 63;
    int rest = lid >> 6;                     // b*49 + l
    int b = rest / LOUT, l = rest - b * LOUT;
    int idx = (b * 64 + l) * 64 + oc;        // padded g_part index (coalesced in oc)
    float s = 0.0f;
#pragma unroll
    for (int i = 0; i < 32; i++) s += g_part[q * 32 + i][idx];
    acc[q][r] = s;
    __syncthreads();
    if (q == 0) {
        float t = acc[0][r] + acc[1][r] + acc[2][r] + acc[3][r]
                + acc[4][r] + acc[5][r] + acc[6][r] + acc[7][r];
        float z = t + bias[oc];
        g_sw[(b * NOC + oc) * LOUT + l] = 1.0f / (1.0f + __expf(-z));
    }

    // L2 prefetch for rs/featmean/head (sink write defeats DCE).
    float pf = 0.0f;
    int gt = blockIdx.x * 256 + tid;         // 392*256 = 100352 threads
    for (int i = gt; i < BB * 512 * 169; i += 392 * 256) pf += featf[i];
    if (gt < 13 * 64 * 5) pf += wf[gt];
    if (gt < 3 * 1536)    pf += hw[gt];
    if (tid == 0) g_sink[blockIdx.x & 0xff] = pf;
}

// ---------------------------------------------------------------------------
// Kernel 4: convf -> r. Warp per (b, pos), direct L2 gathers.
// ---------------------------------------------------------------------------
__global__ void __launch_bounds__(256) rs_kernel(const float* __restrict__ wf,
                                                 const float* __restrict__ bf) {
    int gw = blockIdx.x * 8 + (threadIdx.x >> 5);
    int lane = threadIdx.x & 31;
    if (gw >= BB * 169) return;   // uniform per warp
    int b = gw / 169, pos = gw % 169;
    int j = pos / 13, i = pos % 13;
    const float* swb = g_sw + b * NOC * LOUT;
    float a = 0.0f;
#pragma unroll
    for (int h = 0; h < 2; h++) {
        int ci = lane + h * 32;
        const float* wrow = wf + (j * 64 + ci) * 5;
        const float* srow = swb + ci * LOUT;
#pragma unroll
        for (int tt = 0; tt < 5; tt++) {
            int p = 4 * i - 2 + tt;
            if (p >= 0 && p < LOUT) a += wrow[tt] * srow[p];
        }
    }
#pragma unroll
    for (int o = 16; o; o >>= 1) a += __shfl_xor_sync(0xffffffffu, a, o);
    if (lane == 0) g_rs[b * 169 + pos] = 1.0f / (1.0f + __expf(-(a + bf[j])));
}

// ---------------------------------------------------------------------------
// Kernel 5: attended mean over features_f. 256 blocks, warp per channel.
// ---------------------------------------------------------------------------
__global__ void __launch_bounds__(256) featmean_kernel(const float* __restrict__ featf) {
    __shared__ float rs[169];
    int b = blockIdx.x >> 6, tid = threadIdx.x;
    int c0 = (blockIdx.x & 63) * 8;
    if (tid < 169) rs[tid] = g_rs[b * 169 + tid];
    __syncthreads();
    int wid = tid >> 5, lane = tid & 31;
    int c = c0 + wid;
    const float* fp = featf + (size_t)(b * 512 + c) * 169;
    float s = 0.0f;
#pragma unroll 6
    for (int p = lane; p < 169; p += 32) s += fp[p] * (1.0f + rs[p]);
#pragma unroll
    for (int o = 16; o; o >>= 1) s += __shfl_xor_sync(0xffffffffu, s, o);
    if (lane == 0) g_feat[b * 512 + c] = s * (1.0f / 169.0f);
}

// ---------------------------------------------------------------------------
// Kernel 6: classification head. 12 warps, one per (b, out).
// ---------------------------------------------------------------------------
__global__ void head_kernel(const float* __restrict__ hw, const float* __restrict__ hb,
                            float* __restrict__ out) {
    int wid = threadIdx.x >> 5, lane = threadIdx.x & 31;
    int b = wid / 3, o = wid % 3;
    float s = 0.0f;
    for (int c = lane; c < 1536; c += 32) {
        float f = (c < 512) ? g_feat[b * 512 + c] : g_feato[b * CC2 + (c - 512)];
        s += f * hw[o * 1536 + c];
    }
#pragma unroll
    for (int off = 16; off; off >>= 1) s += __shfl_xor_sync(0xffffffffu, s, off);
    if (lane == 0) out[b * 3 + o] = s + hb[o];
}

// ---------------------------------------------------------------------------
extern "C" void kernel_launch(void* const* d_in, const int* in_sizes, int n_in,
                              void* d_out, int out_size) {
    const float* featf = (const float*)d_in[0];
    const float* oct   = (const float*)d_in[1];
    const float* w1    = (const float*)d_in[2];
    const float* b1    = (const float*)d_in[3];
    const float* wf    = (const float*)d_in[4];
    const float* bf    = (const float*)d_in[5];
    const float* hw    = (const float*)d_in[6];
    const float* hb    = (const float*)d_in[7];
    float* out = (float*)d_out;

    // Three dummy launches: position pool_kernel at launch #4 so ncu's
    // fixed skip count finally profiles the biggest kernel.
    dummy_kernel<<<1, 32>>>();
    dummy_kernel<<<1, 32>>>();
    dummy_kernel<<<1, 32>>>();

    pool_kernel<<<2048, 512>>>(oct);

    const int smem_bytes = (2048 + 2 * 64 * WS_LD) * sizeof(float);
    cudaFuncSetAttribute(gemm_kernel, cudaFuncAttributeMaxDynamicSharedMemorySize,
                         smem_bytes);
    gemm_kernel<<<NSPLIT, 256, smem_bytes>>>(w1);

    reduce_kernel<<<392, 256>>>(b1, wf, hw, featf);
    rs_kernel<<<85, 256>>>(wf, bf);
    featmean_kernel<<<256, 256>>>(featf);
    head_kernel<<<1, 384>>>(hw, hb, out);
}

// round 15
// speedup vs baseline: 1.0666x; 1.0666x over previous
#include <cuda_runtime.h>
#include <cstdint>

#define BB 4
#define MM 112
#define CCH 512
#define CC2 1024
#define LOUT 49
#define NOC 64
#define NSPLIT 256
#define ICPC 4
#define WS_LD 68

__device__ float g_x[BB * CC2 * MM];
__device__ float g_feato[BB * CC2];
__device__ float g_part[NSPLIT][BB * 64 * NOC];
__device__ float g_sw[BB * NOC * LOUT];
__device__ float g_rs[BB * 169];
__device__ float g_feat[BB * 512];
__device__ float g_sink[512];

// ---------------------------------------------------------------------------
// Kernel 1: fused pool + argmax. 512 threads; each warp handles TWO slabs per
// iteration (m, m+16) -> 4 independent float4 loads in flight, pipelined
// shuffle chains. Block per (b,c).
// ---------------------------------------------------------------------------
__global__ void __launch_bounds__(512) pool_kernel(const float* __restrict__ oct) {
    __shared__ float sfv[MM];
    __shared__ float sfm[MM];
    int b = blockIdx.x >> 9, c = blockIdx.x & 511;
    int tid = threadIdx.x, wid = tid >> 5, lane = tid & 31;

    const float4* base = reinterpret_cast<const float4*>(oct);
#pragma unroll
    for (int m = wid; m < MM; m += 32) {
        int m2 = m + 16;
        bool has2 = (m2 < MM);
        const float4* p1 = base + ((size_t)(b * MM + m) * CCH + c) * 64;
        const float4* p2 = base + ((size_t)(b * MM + (has2 ? m2 : m)) * CCH + c) * 64;
        float4 a0 = p1[lane];
        float4 a1 = p1[lane + 32];
        float4 c0 = p2[lane];
        float4 c1 = p2[lane + 32];
        float s1  = (a0.x + a0.y) + (a0.z + a0.w) + (a1.x + a1.y) + (a1.z + a1.w);
        float mx1 = fmaxf(fmaxf(fmaxf(a0.x, a0.y), fmaxf(a0.z, a0.w)),
                          fmaxf(fmaxf(a1.x, a1.y), fmaxf(a1.z, a1.w)));
        float s2  = (c0.x + c0.y) + (c0.z + c0.w) + (c1.x + c1.y) + (c1.z + c1.w);
        float mx2 = fmaxf(fmaxf(fmaxf(c0.x, c0.y), fmaxf(c0.z, c0.w)),
                          fmaxf(fmaxf(c1.x, c1.y), fmaxf(c1.z, c1.w)));
#pragma unroll
        for (int o = 16; o; o >>= 1) {
            s1  += __shfl_xor_sync(0xffffffffu, s1, o);
            s2  += __shfl_xor_sync(0xffffffffu, s2, o);
            mx1  = fmaxf(mx1, __shfl_xor_sync(0xffffffffu, mx1, o));
            mx2  = fmaxf(mx2, __shfl_xor_sync(0xffffffffu, mx2, o));
        }
        if (lane == 0) {
            sfv[m] = s1 * (1.0f / 256.0f); sfm[m] = mx1;
            if (has2) { sfv[m2] = s2 * (1.0f / 256.0f); sfm[m2] = mx2; }
        }
    }
    __syncthreads();

    if (tid < MM) {
        g_x[(b * CC2 + c) * MM + tid]       = sfv[tid];
        g_x[(b * CC2 + 512 + c) * MM + tid] = sfm[tid];
    }

    if (wid == 15) {
        float maxfv = -1e30f, maxfm = -1e30f;
        int idx = 0x7fffffff;
        for (int m = lane; m < MM; m += 32) {
            maxfv = fmaxf(maxfv, sfv[m]);
            float q = sfm[m];
            if (q > maxfm) { maxfm = q; idx = m; }
        }
#pragma unroll
        for (int o = 16; o; o >>= 1) {
            maxfv = fmaxf(maxfv, __shfl_xor_sync(0xffffffffu, maxfv, o));
            float ov = __shfl_xor_sync(0xffffffffu, maxfm, o);
            int   oi = __shfl_xor_sync(0xffffffffu, idx,   o);
            if (ov > maxfm || (ov == maxfm && oi < idx)) { maxfm = ov; idx = oi; }
        }
        if (lane == 0) {
            g_feato[b * CC2 + c]       = maxfv;
            g_feato[b * CC2 + 512 + c] = sfv[idx];
        }
    }
}

// ---------------------------------------------------------------------------
// Kernel 2: split-K tf32 GEMM (cp.async double-buffered W), 256 CTAs.
// ---------------------------------------------------------------------------
__device__ __forceinline__ float to_tf32(float x) {
    uint32_t u;
    asm("cvt.rna.tf32.f32 %0, %1;" : "=r"(u) : "f"(x));
    return __uint_as_float(u);
}

__device__ __forceinline__ void cp16(void* smem_dst, const void* gptr) {
    uint32_t s = (uint32_t)__cvta_generic_to_shared(smem_dst);
    asm volatile("cp.async.cg.shared.global [%0], [%1], 16;" :: "r"(s), "l"(gptr));
}

extern "C" __global__ void __launch_bounds__(256, 2)
gemm_kernel(const float* __restrict__ w) {
    extern __shared__ float sh[];
    float* xs = sh;            // [4][ICPC][128]
    float* ws = sh + 2048;     // [2][64][WS_LD]

    const int tid = threadIdx.x;
    const int split = blockIdx.x;
    const int ic0 = split * ICPC;

#pragma unroll
    for (int i = 0; i < 4; i++) {
        int ii = tid + i * 256;
        int oc = ii >> 4, k4 = ii & 15;
        cp16(ws + oc * WS_LD + k4 * 4,
             w + (size_t)oc * 65536 + (size_t)ic0 * 64 + k4 * 4);
    }
    asm volatile("cp.async.commit_group;");

    for (int i = tid; i < 4 * ICPC * 128; i += 256) {
        int m = i & 127, j = (i >> 7) & (ICPC - 1), b = i >> 9;
        float v = (m < MM) ? g_x[(b * CC2 + ic0 + j) * MM + m] : 0.0f;
        xs[i] = to_tf32(v);
    }

    const int wid = tid >> 5, lane = tid & 31;
    const int b = wid >> 1, mhalf = wid & 1;
    const int g = lane >> 2, t = lane & 3;
    const float* xb = xs + b * ICPC * 128;

    float acc[2][8][4];
#pragma unroll
    for (int a = 0; a < 2; a++)
#pragma unroll
        for (int n = 0; n < 8; n++)
#pragma unroll
            for (int q = 0; q < 4; q++) acc[a][n][q] = 0.0f;

    for (int j = 0; j < ICPC; j++) {
        asm volatile("cp.async.wait_group 0;");
        __syncthreads();
        if (j < ICPC - 1) {
            float* dst = ws + ((j + 1) & 1) * 64 * WS_LD;
#pragma unroll
            for (int i = 0; i < 4; i++) {
                int ii = tid + i * 256;
                int oc = ii >> 4, k4 = ii & 15;
                cp16(dst + oc * WS_LD + k4 * 4,
                     w + (size_t)oc * 65536 + (size_t)(ic0 + j + 1) * 64 + k4 * 4);
            }
            asm volatile("cp.async.commit_group;");
        }
        const float* wb = ws + (j & 1) * 64 * WS_LD;
        const float* xr = xb + j * 128;
#pragma unroll
        for (int k0 = 0; k0 < 64; k0 += 8) {
            uint32_t a0[2], a1[2], a2[2], a3[2];
#pragma unroll
            for (int mt = 0; mt < 2; mt++) {
                int lb = mhalf * 32 + mt * 16 + g;
                a0[mt] = __float_as_uint(xr[lb     + k0 + t]);
                a1[mt] = __float_as_uint(xr[lb + 8 + k0 + t]);
                a2[mt] = __float_as_uint(xr[lb     + k0 + t + 4]);
                a3[mt] = __float_as_uint(xr[lb + 8 + k0 + t + 4]);
            }
#pragma unroll
            for (int nt = 0; nt < 8; nt++) {
                uint32_t b0 = __float_as_uint(wb[(nt * 8 + g) * WS_LD + k0 + t]);
                uint32_t b1 = __float_as_uint(wb[(nt * 8 + g) * WS_LD + k0 + t + 4]);
#pragma unroll
                for (int mt = 0; mt < 2; mt++) {
                    asm volatile(
                        "mma.sync.aligned.m16n8k8.row.col.f32.tf32.tf32.f32 "
                        "{%0,%1,%2,%3}, {%4,%5,%6,%7}, {%8,%9}, {%0,%1,%2,%3};"
                        : "+f"(acc[mt][nt][0]), "+f"(acc[mt][nt][1]),
                          "+f"(acc[mt][nt][2]), "+f"(acc[mt][nt][3])
                        : "r"(a0[mt]), "r"(a1[mt]), "r"(a2[mt]), "r"(a3[mt]),
                          "r"(b0), "r"(b1));
                }
            }
        }
    }

    float* po = &g_part[split][0];
#pragma unroll
    for (int mt = 0; mt < 2; mt++) {
        int row0 = mhalf * 32 + mt * 16 + g;
#pragma unroll
        for (int nt = 0; nt < 8; nt++) {
            int col = nt * 8 + 2 * t;
            if (row0 < LOUT) {
                float2 v01 = make_float2(acc[mt][nt][0], acc[mt][nt][1]);
                *reinterpret_cast<float2*>(po + (size_t)(b * 64 + row0) * 64 + col) = v01;
            }
            if (row0 + 8 < LOUT) {
                float2 v23 = make_float2(acc[mt][nt][2], acc[mt][nt][3]);
                *reinterpret_cast<float2*>(po + (size_t)(b * 64 + row0 + 8) * 64 + col) = v23;
            }
        }
    }
}

// ---------------------------------------------------------------------------
// Kernel 3: split-K reduce (coalesced, dead-l skipped) + L2 prefetch.
// ---------------------------------------------------------------------------
__global__ void __launch_bounds__(256) reduce_kernel(const float* __restrict__ bias,
                                                     const float* __restrict__ wf,
                                                     const float* __restrict__ hw,
                                                     const float* __restrict__ featf) {
    __shared__ float acc[8][32];
    int tid = threadIdx.x;
    int q = tid >> 5, r = tid & 31;
    int idx = blockIdx.x * 32 + r;
    int l = (idx >> 6) & 63;          // warp-uniform
    float s = 0.0f;
    if (l < LOUT) {
#pragma unroll
        for (int i = 0; i < 32; i++) s += g_part[q * 32 + i][idx];
    }
    acc[q][r] = s;
    __syncthreads();
    if (q == 0 && l < LOUT) {
        float t = acc[0][r] + acc[1][r] + acc[2][r] + acc[3][r]
                + acc[4][r] + acc[5][r] + acc[6][r] + acc[7][r];
        int oc = idx & 63, b = idx >> 12;
        float z = t + bias[oc];
        g_sw[(b * NOC + oc) * LOUT + l] = 1.0f / (1.0f + __expf(-z));
    }

    float pf = 0.0f;
    int gt = blockIdx.x * 256 + tid;
    for (int i = gt; i < BB * 512 * 169; i += 512 * 256) pf += featf[i];
    if (gt < 13 * 64 * 5) pf += wf[gt];
    if (gt < 3 * 1536)    pf += hw[gt];
    if (tid == 0) g_sink[blockIdx.x & 0xff] = pf;
}

// ---------------------------------------------------------------------------
// Kernel 4: convf -> r. Warp per (b, pos), direct L2 gathers.
// ---------------------------------------------------------------------------
__global__ void __launch_bounds__(256) rs_kernel(const float* __restrict__ wf,
                                                 const float* __restrict__ bf) {
    int gw = blockIdx.x * 8 + (threadIdx.x >> 5);
    int lane = threadIdx.x & 31;
    if (gw >= BB * 169) return;   // uniform per warp
    int b = gw / 169, pos = gw % 169;
    int j = pos / 13, i = pos % 13;
    const float* swb = g_sw + b * NOC * LOUT;
    float a = 0.0f;
#pragma unroll
    for (int h = 0; h < 2; h++) {
        int ci = lane + h * 32;
        const float* wrow = wf + (j * 64 + ci) * 5;
        const float* srow = swb + ci * LOUT;
#pragma unroll
        for (int tt = 0; tt < 5; tt++) {
            int p = 4 * i - 2 + tt;
            if (p >= 0 && p < LOUT) a += wrow[tt] * srow[p];
        }
    }
#pragma unroll
    for (int o = 16; o; o >>= 1) a += __shfl_xor_sync(0xffffffffu, a, o);
    if (lane == 0) g_rs[b * 169 + pos] = 1.0f / (1.0f + __expf(-(a + bf[j])));
}

// ---------------------------------------------------------------------------
// Kernel 5: attended mean over features_f. 256 blocks, warp per channel.
// ---------------------------------------------------------------------------
__global__ void __launch_bounds__(256) featmean_kernel(const float* __restrict__ featf) {
    __shared__ float rs[169];
    int b = blockIdx.x >> 6, tid = threadIdx.x;
    int c0 = (blockIdx.x & 63) * 8;
    if (tid < 169) rs[tid] = g_rs[b * 169 + tid];
    __syncthreads();
    int wid = tid >> 5, lane = tid & 31;
    int c = c0 + wid;
    const float* fp = featf + (size_t)(b * 512 + c) * 169;
    float s = 0.0f;
#pragma unroll 6
    for (int p = lane; p < 169; p += 32) s += fp[p] * (1.0f + rs[p]);
#pragma unroll
    for (int o = 16; o; o >>= 1) s += __shfl_xor_sync(0xffffffffu, s, o);
    if (lane == 0) g_feat[b * 512 + c] = s * (1.0f / 169.0f);
}

// ---------------------------------------------------------------------------
// Kernel 6: classification head. 12 warps, one per (b, out).
// ---------------------------------------------------------------------------
__global__ void head_kernel(const float* __restrict__ hw, const float* __restrict__ hb,
                            float* __restrict__ out) {
    int wid = threadIdx.x >> 5, lane = threadIdx.x & 31;
    int b = wid / 3, o = wid % 3;
    float s = 0.0f;
    for (int c = lane; c < 1536; c += 32) {
        float f = (c < 512) ? g_feat[b * 512 + c] : g_feato[b * CC2 + (c - 512)];
        s += f * hw[o * 1536 + c];
    }
#pragma unroll
    for (int off = 16; off; off >>= 1) s += __shfl_xor_sync(0xffffffffu, s, off);
    if (lane == 0) out[b * 3 + o] = s + hb[o];
}

// ---------------------------------------------------------------------------
extern "C" void kernel_launch(void* const* d_in, const int* in_sizes, int n_in,
                              void* d_out, int out_size) {
    const float* featf = (const float*)d_in[0];
    const float* oct   = (const float*)d_in[1];
    const float* w1    = (const float*)d_in[2];
    const float* b1    = (const float*)d_in[3];
    const float* wf    = (const float*)d_in[4];
    const float* bf    = (const float*)d_in[5];
    const float* hw    = (const float*)d_in[6];
    const float* hb    = (const float*)d_in[7];
    float* out = (float*)d_out;

    pool_kernel<<<2048, 512>>>(oct);

    const int smem_bytes = (2048 + 2 * 64 * WS_LD) * sizeof(float);
    cudaFuncSetAttribute(gemm_kernel, cudaFuncAttributeMaxDynamicSharedMemorySize,
                         smem_bytes);
    gemm_kernel<<<NSPLIT, 256, smem_bytes>>>(w1);

    reduce_kernel<<<512, 256>>>(b1, wf, hw, featf);
    rs_kernel<<<85, 256>>>(wf, bf);
    featmean_kernel<<<256, 256>>>(featf);
    head_kernel<<<1, 384>>>(hw, hb, out);
}